// round 8
// baseline (speedup 1.0000x reference)
#include <cuda_runtime.h>

#define NR 512
#define NZ 512

// Quad table: qt[ir*512+iz] = (tt[ir][iz], tt[ir][iz+1], tt[ir+1][iz], tt[ir+1][iz+1])
__device__ float4 g_qt[NR * NZ];

__global__ void __launch_bounds__(256) build_qt_kernel(const float* __restrict__ tt) {
    int t = blockIdx.x * blockDim.x + threadIdx.x;   // 262144
    int ir = t >> 9;
    int iz = t & 511;
    if (ir >= NR - 1 || iz >= NZ - 1) return;

    float q11 = __ldg(tt + t);
    float q12 = __ldg(tt + t + 1);
    float q21 = __ldg(tt + t + NZ);
    float q22 = __ldg(tt + t + NZ + 1);

    float4 v;
    v.x = q11; v.y = q12; v.z = q21; v.w = q22;
    __stcg(&g_qt[t], v);
}

// Persistent grid-stride interp: exactly one wave of CTAs (148 SMs x 8 blocks),
// each looping over float4-chunks. Eliminates wave transitions + tail
// quantization; the L1tex queue stays continuously fed.
__global__ void __launch_bounds__(256) interp_kernel(
    const float* __restrict__ r,
    const float* __restrict__ z,
    float* __restrict__ out,
    int n4)
{
    cudaGridDependencySynchronize();

    const float4* r4 = reinterpret_cast<const float4*>(r);
    const float4* z4 = reinterpret_cast<const float4*>(z);
    float4* o4 = reinterpret_cast<float4*>(out);

    int stride = gridDim.x * blockDim.x;

    for (int i = blockIdx.x * blockDim.x + threadIdx.x; i < n4; i += stride) {
        float4 rv = __ldcs(r4 + i);
        float4 zv = __ldcs(z4 + i);

        float rr[4] = {rv.x, rv.y, rv.z, rv.w};
        float zz[4] = {zv.x, zv.y, zv.z, zv.w};

        float fr[4], fz[4];
        int   idx[4];
#pragma unroll
        for (int k = 0; k < 4; k++) {
            float frf = fminf(fmaxf(floorf(rr[k]), 0.0f), (float)(NR - 2));
            float fzf = fminf(fmaxf(floorf(zz[k]), 0.0f), (float)(NZ - 2));
            fr[k] = rr[k] - frf;
            fz[k] = zz[k] - fzf;
            idx[k] = (((int)frf) << 9) + (int)fzf;
        }

        float4 q0 = __ldg(&g_qt[idx[0]]);
        float4 q1 = __ldg(&g_qt[idx[1]]);
        float4 q2 = __ldg(&g_qt[idx[2]]);
        float4 q3 = __ldg(&g_qt[idx[3]]);

        float4 o;
        {
            float wr1 = fr[0], wr0 = 1.0f - fr[0];
            float wz1 = fz[0], wz0 = 1.0f - fz[0];
            o.x = q0.x*(wr0*wz0) + q0.z*(wr1*wz0) + q0.y*(wr0*wz1) + q0.w*(wr1*wz1);
        }
        {
            float wr1 = fr[1], wr0 = 1.0f - fr[1];
            float wz1 = fz[1], wz0 = 1.0f - fz[1];
            o.y = q1.x*(wr0*wz0) + q1.z*(wr1*wz0) + q1.y*(wr0*wz1) + q1.w*(wr1*wz1);
        }
        {
            float wr1 = fr[2], wr0 = 1.0f - fr[2];
            float wz1 = fz[2], wz0 = 1.0f - fz[2];
            o.z = q2.x*(wr0*wz0) + q2.z*(wr1*wz0) + q2.y*(wr0*wz1) + q2.w*(wr1*wz1);
        }
        {
            float wr1 = fr[3], wr0 = 1.0f - fr[3];
            float wz1 = fz[3], wz0 = 1.0f - fz[3];
            o.w = q3.x*(wr0*wz0) + q3.z*(wr1*wz0) + q3.y*(wr0*wz1) + q3.w*(wr1*wz1);
        }

        __stcs(o4 + i, o);
    }
}

extern "C" void kernel_launch(void* const* d_in, const int* in_sizes, int n_in,
                              void* d_out, int out_size) {
    const float* r  = (const float*)d_in[0];
    const float* z  = (const float*)d_in[1];
    const float* tt = (const float*)d_in[2];
    float* out = (float*)d_out;

    int n = in_sizes[0];          // 20,000,000
    int n4 = n / 4;               // 5,000,000

    build_qt_kernel<<<(NR * NZ) / 256, 256>>>(tt);

    // Persistent single wave: 148 SMs x 8 CTAs of 256 threads (occupancy 8).
    int threads = 256;
    int blocks = 148 * 8;

    cudaLaunchAttribute attrs[1];
    attrs[0].id = cudaLaunchAttributeProgrammaticStreamSerialization;
    attrs[0].val.programmaticStreamSerializationAllowed = 1;

    cudaLaunchConfig_t cfg = {};
    cfg.gridDim = dim3((unsigned)blocks);
    cfg.blockDim = dim3((unsigned)threads);
    cfg.dynamicSmemBytes = 0;
    cfg.stream = 0;
    cfg.attrs = attrs;
    cfg.numAttrs = 1;

    cudaLaunchKernelEx(&cfg, interp_kernel, r, z, out, n4);
}

// round 9
// speedup vs baseline: 1.0226x; 1.0226x over previous
#include <cuda_runtime.h>

#define NR 512
#define NZ 512

// Quad table: qt[ir*512+iz] = (tt[ir][iz], tt[ir][iz+1], tt[ir+1][iz], tt[ir+1][iz+1])
__device__ float4 g_qt[NR * NZ];

__global__ void __launch_bounds__(256) build_qt_kernel(const float* __restrict__ tt) {
    // Fire the programmatic-launch-completion event immediately: the interp
    // grid may begin launching and running its prolog while we build the
    // table. Memory ordering is provided by interp's griddepsync.
    cudaTriggerProgrammaticLaunchCompletion();

    int t = blockIdx.x * blockDim.x + threadIdx.x;   // 262144
    int ir = t >> 9;
    int iz = t & 511;
    if (ir >= NR - 1 || iz >= NZ - 1) return;

    float q11 = __ldg(tt + t);
    float q12 = __ldg(tt + t + 1);
    float q21 = __ldg(tt + t + NZ);
    float q22 = __ldg(tt + t + NZ + 1);

    float4 v;
    v.x = q11; v.y = q12; v.z = q21; v.w = q22;
    g_qt[t] = v;
}

// 4 points/thread (proven fastest: regs=32, ~full occupancy, L1tex floor).
// PDL: prolog (streaming loads + index math) overlaps build execution;
// cudaGridDependencySynchronize() guards the quad-table gathers.
__global__ void __launch_bounds__(256) interp_kernel(
    const float* __restrict__ r,
    const float* __restrict__ z,
    float* __restrict__ out,
    int n4)
{
    int i = blockIdx.x * blockDim.x + threadIdx.x;
    if (i >= n4) {
        cudaGridDependencySynchronize();
        return;
    }

    float4 rv = __ldcs(reinterpret_cast<const float4*>(r) + i);
    float4 zv = __ldcs(reinterpret_cast<const float4*>(z) + i);

    float rr[4] = {rv.x, rv.y, rv.z, rv.w};
    float zz[4] = {zv.x, zv.y, zv.z, zv.w};

    float fr[4], fz[4];
    int   idx[4];
#pragma unroll
    for (int k = 0; k < 4; k++) {
        float frf = fminf(fmaxf(floorf(rr[k]), 0.0f), (float)(NR - 2));
        float fzf = fminf(fmaxf(floorf(zz[k]), 0.0f), (float)(NZ - 2));
        fr[k] = rr[k] - frf;
        fz[k] = zz[k] - fzf;
        idx[k] = (((int)frf) << 9) + (int)fzf;
    }

    // Wait for build_qt_kernel's memory to be visible before gathering.
    cudaGridDependencySynchronize();

    float res[4];
#pragma unroll
    for (int k = 0; k < 4; k++) {
        float4 q = __ldg(&g_qt[idx[k]]);
        float wr1 = fr[k], wr0 = 1.0f - fr[k];
        float wz1 = fz[k], wz0 = 1.0f - fz[k];
        res[k] = q.x * (wr0 * wz0)
               + q.z * (wr1 * wz0)
               + q.y * (wr0 * wz1)
               + q.w * (wr1 * wz1);
    }

    float4 o;
    o.x = res[0]; o.y = res[1]; o.z = res[2]; o.w = res[3];
    __stcs(reinterpret_cast<float4*>(out) + i, o);
}

extern "C" void kernel_launch(void* const* d_in, const int* in_sizes, int n_in,
                              void* d_out, int out_size) {
    const float* r  = (const float*)d_in[0];
    const float* z  = (const float*)d_in[1];
    const float* tt = (const float*)d_in[2];
    float* out = (float*)d_out;

    int n = in_sizes[0];          // 20,000,000
    int n4 = n / 4;               // 5,000,000

    build_qt_kernel<<<(NR * NZ) / 256, 256>>>(tt);

    int threads = 256;
    int blocks = (n4 + threads - 1) / threads;

    // PDL: interp launches as soon as build fires its trigger; device-side
    // griddepsync provides the ordering for the quad-table reads.
    cudaLaunchAttribute attrs[1];
    attrs[0].id = cudaLaunchAttributeProgrammaticStreamSerialization;
    attrs[0].val.programmaticStreamSerializationAllowed = 1;

    cudaLaunchConfig_t cfg = {};
    cfg.gridDim = dim3((unsigned)blocks);
    cfg.blockDim = dim3((unsigned)threads);
    cfg.dynamicSmemBytes = 0;
    cfg.stream = 0;
    cfg.attrs = attrs;
    cfg.numAttrs = 1;

    cudaLaunchKernelEx(&cfg, interp_kernel, r, z, out, n4);
}